// round 13
// baseline (speedup 1.0000x reference)
#include <cuda_runtime.h>

// VQ-VAE quantizer, round 13: TPT=4 x k-pair f32x2 (zero swaps) + lean
// branchless m1/m2 margin screen + exact warp-cooperative rescue.
//   h: (256,512,32) f32 -> 131072 tokens x 32;  embeddings: (1024,32) f32
//   out f32: qst (131072*32) | indices (131072) | loss (131072)
//
// Model: FFMA2 (3 u64 operands) pays RF-bank rt=3 -> pipe floor 340K cyc/SM
// (179us). Config minimizes everything else: TPT=4 keeps LDS at 16 LDS.128
// per 2-code tile (2 wf each), k-pair packing needs zero lane-swap MOVs,
// epilogue is 1 FSETP/SEL + 3 FMNMX (alu pipe) + 2 fma ops per dot.
// Screen keys use k-split dots (err < ~4e-6 vs reference chain); tokens with
// m2 < m1 + 1e-5 get an exact sequential-fp32 rescan (R5-verified expression
// tree, first-index ties) — empirically validated in R12 (bit-identical
// rel_err). Outputs always use the exact reference fp32 math.

typedef unsigned long long u64;
typedef unsigned int u32;

#define DIM    32
#define NCODES 1024
#define NTOK   131072
#define TPB    256
#define TPT    4
#define NBLK   148
#define TOKPB  886           // 148*886 >= NTOK; 256*4=1024 >= 886 (clamped dups)
#define MARGIN 1e-5f

__device__ __forceinline__ void upk2(u64 v, float& lo, float& hi) {
    asm("mov.b64 {%0, %1}, %2;" : "=f"(lo), "=f"(hi) : "l"(v));
}
__device__ __forceinline__ u64 pk2(float lo, float hi) {
    u64 r;
    asm("mov.b64 %0, {%1, %2};" : "=l"(r) : "f"(lo), "f"(hi));
    return r;
}
__device__ __forceinline__ u64 ffma2(u64 a, u64 b, u64 c) {
    u64 d;
    asm("fma.rn.f32x2 %0, %1, %2, %3;" : "=l"(d) : "l"(a), "l"(b), "l"(c));
    return d;
}

// ||x||^2, reference-order reduction (R5-verified bit-exact).
__device__ __forceinline__ float sumsq32(const float* x) {
    float A0 = __fmul_rn(x[0], x[0]), A1 = __fmul_rn(x[1], x[1]);
    float A2 = __fmul_rn(x[2], x[2]), A3 = __fmul_rn(x[3], x[3]);
#pragma unroll
    for (int i = 1; i < 8; i++) {
        A0 = __fadd_rn(A0, __fmul_rn(x[4*i+0], x[4*i+0]));
        A1 = __fadd_rn(A1, __fmul_rn(x[4*i+1], x[4*i+1]));
        A2 = __fadd_rn(A2, __fmul_rn(x[4*i+2], x[4*i+2]));
        A3 = __fadd_rn(A3, __fmul_rn(x[4*i+3], x[4*i+3]));
    }
    return __fadd_rn(__fadd_rn(A0, A1), __fadd_rn(A2, A3));
}
__device__ __forceinline__ float sumsqdiff32(const float* q, const float* h) {
    float A0, A1, A2, A3;
    {
        float d0 = __fsub_rn(q[0], h[0]), d1 = __fsub_rn(q[1], h[1]);
        float d2 = __fsub_rn(q[2], h[2]), d3 = __fsub_rn(q[3], h[3]);
        A0 = __fmul_rn(d0, d0); A1 = __fmul_rn(d1, d1);
        A2 = __fmul_rn(d2, d2); A3 = __fmul_rn(d3, d3);
    }
#pragma unroll
    for (int i = 1; i < 8; i++) {
        float e0 = __fsub_rn(q[4*i+0], h[4*i+0]), e1 = __fsub_rn(q[4*i+1], h[4*i+1]);
        float e2 = __fsub_rn(q[4*i+2], h[4*i+2]), e3 = __fsub_rn(q[4*i+3], h[4*i+3]);
        A0 = __fadd_rn(A0, __fmul_rn(e0, e0));
        A1 = __fadd_rn(A1, __fmul_rn(e1, e1));
        A2 = __fadd_rn(A2, __fmul_rn(e2, e2));
        A3 = __fadd_rn(A3, __fmul_rn(e3, e3));
    }
    return __fadd_rn(__fadd_rn(A0, A1), __fadd_rn(A2, A3));
}

extern __shared__ float smf[];   // sE[1024][32] natural, then bn[1024]

__global__ void __launch_bounds__(TPB, 1)
vq_kernel(const float* __restrict__ H, const float* __restrict__ E,
          float* __restrict__ out) {
    float* sE = smf;
    float* bn = smf + NCODES * DIM;
    const int tid = threadIdx.x, lane = tid & 31;

    // ---- table: natural layout copy + exact norms ----
    for (int r = tid; r < NCODES; r += TPB) {
        float e[DIM];
        const float4* ep = (const float4*)(E + (size_t)r * DIM);
        float4* sp = (float4*)(sE + (size_t)r * DIM);
#pragma unroll
        for (int v = 0; v < 8; v++) {
            float4 x = ep[v];
            sp[v] = x;
            e[4*v+0] = x.x; e[4*v+1] = x.y; e[4*v+2] = x.z; e[4*v+3] = x.w;
        }
        bn[r] = sumsq32(e);
    }
    __syncthreads();

    // ---- 4 tokens per thread, k-pair packed h (clamped dups are benign) ----
    int t0 = blockIdx.x * TOKPB + tid * TPT;
    if (t0 > NTOK - TPT) t0 = NTOK - TPT;

    u64 hk[TPT][16];
    float a[TPT];
#pragma unroll
    for (int t = 0; t < TPT; t++) {
        float h[DIM];
        const float4* hp = (const float4*)(H + (size_t)(t0 + t) * DIM);
#pragma unroll
        for (int v = 0; v < 8; v++) {
            float4 x = hp[v];
            h[4*v+0] = x.x; h[4*v+1] = x.y; h[4*v+2] = x.z; h[4*v+3] = x.w;
            hk[t][2*v]   = pk2(x.x, x.y);
            hk[t][2*v+1] = pk2(x.z, x.w);
        }
        a[t] = sumsq32(h);
    }

    // ---- screen: min1 (value+idx) + streaming min2 per token ----
    const float INFP = __int_as_float(0x7f800000);
    float m1[TPT], m2[TPT];
    int ix[TPT];
#pragma unroll
    for (int t = 0; t < TPT; t++) { m1[t] = INFP; m2[t] = INFP; ix[t] = 0; }

#pragma unroll 1
    for (int c = 0; c < NCODES; c += 2) {         // 2-code tiles, 8 acc chains
        const ulonglong2* r0 = (const ulonglong2*)(sE + (size_t)(c + 0) * DIM);
        const ulonglong2* r1 = (const ulonglong2*)(sE + (size_t)(c + 1) * DIM);

        u64 a0_0 = 0, a0_1 = 0, a0_2 = 0, a0_3 = 0;   // code c, tokens 0-3
        u64 a1_0 = 0, a1_1 = 0, a1_2 = 0, a1_3 = 0;   // code c+1

#pragma unroll
        for (int j = 0; j < 8; j++) {                 // k = 4j .. 4j+3
            ulonglong2 v0 = r0[j], v1 = r1[j];
            const u64 p0 = hk[0][2*j], q0 = hk[0][2*j+1];
            const u64 p1 = hk[1][2*j], q1 = hk[1][2*j+1];
            const u64 p2 = hk[2][2*j], q2 = hk[2][2*j+1];
            const u64 p3 = hk[3][2*j], q3 = hk[3][2*j+1];
            a0_0 = ffma2(v0.y, q0, ffma2(v0.x, p0, a0_0));
            a0_1 = ffma2(v0.y, q1, ffma2(v0.x, p1, a0_1));
            a0_2 = ffma2(v0.y, q2, ffma2(v0.x, p2, a0_2));
            a0_3 = ffma2(v0.y, q3, ffma2(v0.x, p3, a0_3));
            a1_0 = ffma2(v1.y, q0, ffma2(v1.x, p0, a1_0));
            a1_1 = ffma2(v1.y, q1, ffma2(v1.x, p1, a1_1));
            a1_2 = ffma2(v1.y, q2, ffma2(v1.x, p2, a1_2));
            a1_3 = ffma2(v1.y, q3, ffma2(v1.x, p3, a1_3));
        }

        const float2 b2 = *(const float2*)(bn + c);
        u64 accs[2][TPT] = {{a0_0, a0_1, a0_2, a0_3}, {a1_0, a1_1, a1_2, a1_3}};
#pragma unroll
        for (int cc = 0; cc < 2; cc++) {
            const float bnc = cc ? b2.y : b2.x;
            const int  code = c + cc;
#pragma unroll
            for (int t = 0; t < TPT; t++) {
                float lo, hi;
                upk2(accs[cc][t], lo, hi);
                float dot = __fadd_rn(lo, hi);
                float key = __fmaf_rn(dot, -2.0f, __fadd_rn(a[t], bnc));
                ix[t] = (key < m1[t]) ? code : ix[t];   // strict <: first idx
                m2[t] = fminf(m2[t], fmaxf(m1[t], key));
                m1[t] = fminf(m1[t], key);
            }
        }
    }

    // ---- exact rescue for ambiguous tokens (R12-verified) ----
#pragma unroll
    for (int t = 0; t < TPT; t++) {
        u32 bal = __ballot_sync(0xffffffffu, m2[t] < __fadd_rn(m1[t], MARGIN));
        while (bal) {
            const int src = __ffs(bal) - 1;
            bal &= bal - 1;
            float hr[DIM];
#pragma unroll
            for (int j = 0; j < 16; j++) {
                u64 v = __shfl_sync(0xffffffffu, hk[t][j], src);
                upk2(v, hr[2*j], hr[2*j+1]);
            }
            const float at = __shfl_sync(0xffffffffu, a[t], src);
            float bd = INFP;
            int bix = 0;
#pragma unroll 1
            for (int w = 0; w < 32; w++) {
                const int code = lane + 32 * w;            // ascending per lane
                const float4* er = (const float4*)(sE + (size_t)code * DIM);
                float acc = 0.0f;                          // reference chain
#pragma unroll
                for (int v = 0; v < 8; v++) {
                    float4 x = er[v];
                    acc = __fmaf_rn(x.x, hr[4*v+0], acc);
                    acc = __fmaf_rn(x.y, hr[4*v+1], acc);
                    acc = __fmaf_rn(x.z, hr[4*v+2], acc);
                    acc = __fmaf_rn(x.w, hr[4*v+3], acc);
                }
                float dd = __fmaf_rn(acc, -2.0f, __fadd_rn(at, bn[code]));
                if (dd < bd) { bd = dd; bix = code; }
            }
#pragma unroll
            for (int o = 16; o; o >>= 1) {
                float od = __shfl_xor_sync(0xffffffffu, bd, o);
                int   oi = __shfl_xor_sync(0xffffffffu, bix, o);
                if (od < bd || (od == bd && oi < bix)) { bd = od; bix = oi; }
            }
            if (lane == src) ix[t] = bix;
        }
    }

    // ---- exact outputs (identical fp32 math to R5) ----
#pragma unroll
    for (int t = 0; t < TPT; t++) {
        const int tok = t0 + t;
        float h[DIM], q[DIM];
#pragma unroll
        for (int j = 0; j < 16; j++) upk2(hk[t][j], h[2*j], h[2*j+1]);
        const float4* qp = (const float4*)(sE + (size_t)ix[t] * DIM);
#pragma unroll
        for (int v = 0; v < 8; v++) {
            float4 x = qp[v];
            q[4*v+0] = x.x; q[4*v+1] = x.y; q[4*v+2] = x.z; q[4*v+3] = x.w;
        }
        float ss = sumsqdiff32(q, h);
        float L  = __fmul_rn(ss, 0.03125f);
        float l1 = __fmul_rn(L, 0.1f);
        float loss = __fadd_rn(l1, l1);

        float4* oq = (float4*)(out + (size_t)tok * DIM);
#pragma unroll
        for (int v = 0; v < 8; v++) {
            float4 r;
            r.x = __fadd_rn(h[4*v+0], __fsub_rn(q[4*v+0], h[4*v+0]));
            r.y = __fadd_rn(h[4*v+1], __fsub_rn(q[4*v+1], h[4*v+1]));
            r.z = __fadd_rn(h[4*v+2], __fsub_rn(q[4*v+2], h[4*v+2]));
            r.w = __fadd_rn(h[4*v+3], __fsub_rn(q[4*v+3], h[4*v+3]));
            oq[v] = r;
        }
        out[(size_t)NTOK * DIM + tok] = (float)ix[t];
        out[(size_t)NTOK * DIM + NTOK + tok] = loss;
    }
}

extern "C" void kernel_launch(void* const* d_in, const int* in_sizes, int n_in,
                              void* d_out, int out_size) {
    (void)in_sizes; (void)n_in; (void)out_size;
    size_t smem = (size_t)(NCODES * DIM + NCODES) * sizeof(float);  // 135168 B
    cudaFuncSetAttribute(vq_kernel, cudaFuncAttributeMaxDynamicSharedMemorySize,
                         (int)smem);
    vq_kernel<<<NBLK, TPB, smem>>>((const float*)d_in[0], (const float*)d_in[1],
                                   (float*)d_out);
}

// round 14
// speedup vs baseline: 1.2166x; 1.2166x over previous
#include <cuda_runtime.h>

// VQ-VAE quantizer, round 14: R9 structure with the lane-swap MOVs deleted.
//   h: (256,512,32) f32 -> 131072 tokens x 32;  embeddings: (1024,32) f32
//   out f32: qst (131072*32) | indices (131072) | loss (131072)
//
// Slot model (fits R6/R9/R12/R13): FFMA2 costs ~3 issue-slot-cycles (3
// distinct u64 operands -> RF-bank rt=3); floor 340K cyc/SMSP. R9 (best,
// 215.5us) additionally spends 28K cyc on swp2 MOVs + fat epilogue. This
// round stores BOTH the pair-interleaved table AND its lane-swapped copy in
// smem (two 256-pair passes to fit 132KB), so cross-product chains load the
// swapped value directly: zero MOVs in the hot loop, swapped norms also
// precomputed. TPT=4, TPB=224 (1.2% dup work vs R13's 15.6%).
//
// All dot chains are exact sequential reference-order fp32 (R5-verified
// expression tree); argmin in ascending code order with strict < -> no
// screen or rescue needed. f32x2 lanes are IEEE-scalar-identical.

typedef unsigned long long u64;

#define DIM     32
#define NCODES  1024
#define NTOK    131072
#define TPB     224          // 7 warps, all active
#define NBLK    148
#define TPT     4
#define NPAIRH  256          // code-pairs per pass (512 codes)

// smem layout in u64 units
#define EN_O    0            // sEN[256][32]  (e_even, e_odd)
#define ES_O    8192         // sES[256][32]  (e_odd,  e_even)
#define NN_O    16384        // nN[256] = (b_even, b_odd)
#define NS_O    16640        // nS[256] = (b_odd,  b_even)
#define SMEMU   16896        // *8 = 135168 B

__device__ __forceinline__ u64 pk2(float lo, float hi) {
    u64 r;
    asm("mov.b64 %0, {%1, %2};" : "=l"(r) : "f"(lo), "f"(hi));
    return r;
}
__device__ __forceinline__ void upk2(u64 v, float& lo, float& hi) {
    asm("mov.b64 {%0, %1}, %2;" : "=f"(lo), "=f"(hi) : "l"(v));
}
__device__ __forceinline__ u64 ffma2(u64 a, u64 b, u64 c) {
    u64 d;
    asm("fma.rn.f32x2 %0, %1, %2, %3;" : "=l"(d) : "l"(a), "l"(b), "l"(c));
    return d;
}
__device__ __forceinline__ u64 fadd2(u64 a, u64 b) {
    u64 d;
    asm("add.rn.f32x2 %0, %1, %2;" : "=l"(d) : "l"(a), "l"(b));
    return d;
}

// ||x||^2, reference-order reduction (R5-verified bit-exact).
__device__ __forceinline__ float sumsq32(const float* x) {
    float A0 = __fmul_rn(x[0], x[0]), A1 = __fmul_rn(x[1], x[1]);
    float A2 = __fmul_rn(x[2], x[2]), A3 = __fmul_rn(x[3], x[3]);
#pragma unroll
    for (int i = 1; i < 8; i++) {
        A0 = __fadd_rn(A0, __fmul_rn(x[4*i+0], x[4*i+0]));
        A1 = __fadd_rn(A1, __fmul_rn(x[4*i+1], x[4*i+1]));
        A2 = __fadd_rn(A2, __fmul_rn(x[4*i+2], x[4*i+2]));
        A3 = __fadd_rn(A3, __fmul_rn(x[4*i+3], x[4*i+3]));
    }
    return __fadd_rn(__fadd_rn(A0, A1), __fadd_rn(A2, A3));
}
__device__ __forceinline__ float sumsqdiff32(const float* q, const float* h) {
    float A0, A1, A2, A3;
    {
        float d0 = __fsub_rn(q[0], h[0]), d1 = __fsub_rn(q[1], h[1]);
        float d2 = __fsub_rn(q[2], h[2]), d3 = __fsub_rn(q[3], h[3]);
        A0 = __fmul_rn(d0, d0); A1 = __fmul_rn(d1, d1);
        A2 = __fmul_rn(d2, d2); A3 = __fmul_rn(d3, d3);
    }
#pragma unroll
    for (int i = 1; i < 8; i++) {
        float e0 = __fsub_rn(q[4*i+0], h[4*i+0]), e1 = __fsub_rn(q[4*i+1], h[4*i+1]);
        float e2 = __fsub_rn(q[4*i+2], h[4*i+2]), e3 = __fsub_rn(q[4*i+3], h[4*i+3]);
        A0 = __fadd_rn(A0, __fmul_rn(e0, e0));
        A1 = __fadd_rn(A1, __fmul_rn(e1, e1));
        A2 = __fadd_rn(A2, __fmul_rn(e2, e2));
        A3 = __fadd_rn(A3, __fmul_rn(e3, e3));
    }
    return __fadd_rn(__fadd_rn(A0, A1), __fadd_rn(A2, A3));
}

extern __shared__ u64 sm[];

// Finish one token: q gathered from GLOBAL E (winner may be in either pass).
__device__ __forceinline__ void finish_token(int tok, int bi, const u64* hh,
                                             int half, const float* __restrict__ E,
                                             float* __restrict__ out) {
    float q[DIM], h[DIM];
    const float4* qp = (const float4*)(E + (size_t)bi * DIM);
#pragma unroll
    for (int v = 0; v < 8; v++) {
        float4 x = qp[v];
        q[4*v+0] = x.x; q[4*v+1] = x.y; q[4*v+2] = x.z; q[4*v+3] = x.w;
    }
#pragma unroll
    for (int k = 0; k < DIM; k++) {
        float hl, hr;
        upk2(hh[k], hl, hr);
        h[k] = half ? hr : hl;
    }
    float ss = sumsqdiff32(q, h);
    float L  = __fmul_rn(ss, 0.03125f);     // /32 exact
    float l1 = __fmul_rn(L, 0.1f);
    float loss = __fadd_rn(l1, l1);

    float4* oq = (float4*)(out + (size_t)tok * DIM);
#pragma unroll
    for (int v = 0; v < 8; v++) {
        float4 r;
        r.x = __fadd_rn(h[4*v+0], __fsub_rn(q[4*v+0], h[4*v+0]));
        r.y = __fadd_rn(h[4*v+1], __fsub_rn(q[4*v+1], h[4*v+1]));
        r.z = __fadd_rn(h[4*v+2], __fsub_rn(q[4*v+2], h[4*v+2]));
        r.w = __fadd_rn(h[4*v+3], __fsub_rn(q[4*v+3], h[4*v+3]));
        oq[v] = r;
    }
    out[(size_t)NTOK * DIM + tok] = (float)bi;
    out[(size_t)NTOK * DIM + NTOK + tok] = loss;
}

__global__ void __launch_bounds__(TPB, 1)
vq_kernel(const float* __restrict__ H, const float* __restrict__ E,
          float* __restrict__ out) {
    const int tid = threadIdx.x;
    const int gid = blockIdx.x * TPB + tid;
    int t0 = gid * TPT;
    if (t0 > NTOK - TPT) t0 = NTOK - TPT;   // tail dup: identical writes

    // ---- 4 tokens as two token-pair packed register sets ----
    u64 hhA[DIM], hhB[DIM];
    float a0, a1, a2, a3;
    {
        float x[DIM], y[DIM];
#pragma unroll
        for (int pair = 0; pair < 2; pair++) {
            const float4* p0 = (const float4*)(H + (size_t)(t0 + 2*pair) * DIM);
            const float4* p1 = p0 + 8;
            u64* hh = pair ? hhB : hhA;
#pragma unroll
            for (int v = 0; v < 8; v++) {
                float4 u = p0[v], w = p1[v];
                x[4*v+0] = u.x; x[4*v+1] = u.y; x[4*v+2] = u.z; x[4*v+3] = u.w;
                y[4*v+0] = w.x; y[4*v+1] = w.y; y[4*v+2] = w.z; y[4*v+3] = w.w;
                hh[4*v+0] = pk2(u.x, w.x); hh[4*v+1] = pk2(u.y, w.y);
                hh[4*v+2] = pk2(u.z, w.z); hh[4*v+3] = pk2(u.w, w.w);
            }
            if (pair) { a2 = sumsq32(x); a3 = sumsq32(y); }
            else      { a0 = sumsq32(x); a1 = sumsq32(y); }
        }
    }
    const u64 aA   = pk2(a0, a1);
    const u64 aB   = pk2(a2, a3);
    const u64 neg2 = pk2(-2.0f, -2.0f);

    const float INFP = __int_as_float(0x7f800000);
    float bb0 = INFP, bb1 = INFP, bb2 = INFP, bb3 = INFP;
    int bi0 = 0, bi1 = 0, bi2 = 0, bi3 = 0;

    // ---- two passes over 512-code half-tables (normal + swapped copies) ----
#pragma unroll 1
    for (int pass = 0; pass < 2; pass++) {
        if (pass) __syncthreads();   // drain pass-0 reads before overwrite
        for (int p = tid; p < NPAIRH; p += TPB) {
            const int c0 = pass * 512 + 2 * p;
            float e0[DIM], e1[DIM];
            const float4* r0 = (const float4*)(E + (size_t)c0 * DIM);
            const float4* r1 = (const float4*)(E + (size_t)(c0 + 1) * DIM);
#pragma unroll
            for (int v = 0; v < 8; v++) {
                float4 x = r0[v];
                e0[4*v+0] = x.x; e0[4*v+1] = x.y; e0[4*v+2] = x.z; e0[4*v+3] = x.w;
                float4 y = r1[v];
                e1[4*v+0] = y.x; e1[4*v+1] = y.y; e1[4*v+2] = y.z; e1[4*v+3] = y.w;
            }
#pragma unroll
            for (int k = 0; k < DIM; k++) {
                sm[EN_O + p * DIM + k] = pk2(e0[k], e1[k]);
                sm[ES_O + p * DIM + k] = pk2(e1[k], e0[k]);
            }
            float b0 = sumsq32(e0), b1 = sumsq32(e1);
            sm[NN_O + p] = pk2(b0, b1);
            sm[NS_O + p] = pk2(b1, b0);
        }
        __syncthreads();

        // ---- main: 2 code-pairs x 4 tokens per tile; zero swaps ----
#pragma unroll 1
        for (int p0 = 0; p0 < NPAIRH; p0 += 2) {
            const ulonglong2* vN0 = (const ulonglong2*)&sm[EN_O + p0 * DIM];
            const ulonglong2* vN1 = vN0 + 16;
            const ulonglong2* vS0 = (const ulonglong2*)&sm[ES_O + p0 * DIM];
            const ulonglong2* vS1 = vS0 + 16;

            u64 AO0 = 0, AS0 = 0, BO0 = 0, BS0 = 0;
            u64 AO1 = 0, AS1 = 0, BO1 = 0, BS1 = 0;
#pragma unroll
            for (int j = 0; j < 16; j++) {       // k = 2j, 2j+1 sequential
                ulonglong2 n0 = vN0[j], s0 = vS0[j];
                ulonglong2 n1 = vN1[j], s1 = vS1[j];
                const u64 ha = hhA[2*j], hb = hhA[2*j+1];
                const u64 ga = hhB[2*j], gb = hhB[2*j+1];
                AO0 = ffma2(n0.y, hb, ffma2(n0.x, ha, AO0));
                AS0 = ffma2(s0.y, hb, ffma2(s0.x, ha, AS0));
                BO0 = ffma2(n0.y, gb, ffma2(n0.x, ga, BO0));
                BS0 = ffma2(s0.y, gb, ffma2(s0.x, ga, BS0));
                AO1 = ffma2(n1.y, hb, ffma2(n1.x, ha, AO1));
                AS1 = ffma2(s1.y, hb, ffma2(s1.x, ha, AS1));
                BO1 = ffma2(n1.y, gb, ffma2(n1.x, ga, BO1));
                BS1 = ffma2(s1.y, gb, ffma2(s1.x, ga, BS1));
            }

            u64 AO[2] = {AO0, AO1}, AS[2] = {AS0, AS1};
            u64 BO[2] = {BO0, BO1}, BS[2] = {BS0, BS1};
#pragma unroll
            for (int u = 0; u < 2; u++) {
                const u64 nN = sm[NN_O + p0 + u];
                const u64 nS = sm[NS_O + p0 + u];
                // dist = fl(fl(a+b) - 2*dot); all lanes exact reference math
                u64 dAO = ffma2(AO[u], neg2, fadd2(aA, nN)); // (t0,ce) (t1,co)
                u64 dAS = ffma2(AS[u], neg2, fadd2(aA, nS)); // (t0,co) (t1,ce)
                u64 dBO = ffma2(BO[u], neg2, fadd2(aB, nN)); // (t2,ce) (t3,co)
                u64 dBS = ffma2(BS[u], neg2, fadd2(aB, nS)); // (t2,co) (t3,ce)
                float x0, x1, y0, y1, z0, z1, w0, w1;
                upk2(dAO, x0, x1);
                upk2(dAS, y0, y1);
                upk2(dBO, z0, z1);
                upk2(dBS, w0, w1);
                const int j0 = pass * 512 + (p0 + u) * 2, j1 = j0 + 1;
                if (x0 < bb0) { bb0 = x0; bi0 = j0; }   // ascending: even,odd
                if (y0 < bb0) { bb0 = y0; bi0 = j1; }
                if (y1 < bb1) { bb1 = y1; bi1 = j0; }
                if (x1 < bb1) { bb1 = x1; bi1 = j1; }
                if (z0 < bb2) { bb2 = z0; bi2 = j0; }
                if (w0 < bb2) { bb2 = w0; bi2 = j1; }
                if (w1 < bb3) { bb3 = w1; bi3 = j0; }
                if (z1 < bb3) { bb3 = z1; bi3 = j1; }
            }
        }
    }

    // ---- exact outputs (identical fp32 math to R5) ----
    finish_token(t0 + 0, bi0, hhA, 0, E, out);
    finish_token(t0 + 1, bi1, hhA, 1, E, out);
    finish_token(t0 + 2, bi2, hhB, 0, E, out);
    finish_token(t0 + 3, bi3, hhB, 1, E, out);
}

extern "C" void kernel_launch(void* const* d_in, const int* in_sizes, int n_in,
                              void* d_out, int out_size) {
    (void)in_sizes; (void)n_in; (void)out_size;
    size_t smem = (size_t)SMEMU * sizeof(u64);   // 135168 B
    cudaFuncSetAttribute(vq_kernel, cudaFuncAttributeMaxDynamicSharedMemorySize,
                         (int)smem);
    vq_kernel<<<NBLK, TPB, smem>>>((const float*)d_in[0], (const float*)d_in[1],
                                   (float*)d_out);
}